// round 10
// baseline (speedup 1.0000x reference)
#include <cuda_runtime.h>
#include <cuda_fp16.h>
#include <math.h>
#include <stdint.h>

#define BROWS 8192
#define DIM   256
#define RSB   528           // smem row stride bytes (256 halves + 8 pad)
#define ATILE (128 * RSB)   // 67584 B per tile slot
#define NCTA  148
#define NTHR  512
#define NWARP (NTHR / 32)
#define TOTW  (NCTA * NWARP)

static __device__ __constant__ float kEPS = 1e-8f;

// ------------------------- device scratch ----------------------------------
__device__ __align__(16) __half g_xh[BROWS * DIM];   // normalized fp16 (4 MB)
__device__ float                g_inv[BROWS];        // per-row 1/norm
__device__ unsigned long long   g_best[BROWS];
__device__ unsigned             g_barc[2];           // generation barrier counters

// ------------------------- helpers -----------------------------------------
__device__ __forceinline__ uint32_t smem_u32(const void* p) {
    uint32_t a;
    asm("{ .reg .u64 t; cvta.to.shared.u64 t, %1; cvt.u32.u64 %0, t; }" : "=r"(a) : "l"(p));
    return a;
}
__device__ __forceinline__ void ldsm4(uint32_t r[4], uint32_t a) {
    asm volatile("ldmatrix.sync.aligned.m8n8.x4.shared.b16 {%0,%1,%2,%3}, [%4];"
                 : "=r"(r[0]), "=r"(r[1]), "=r"(r[2]), "=r"(r[3]) : "r"(a));
}
__device__ __forceinline__ void mma16816h(uint32_t c[2], const uint32_t a[4],
                                          uint32_t b0, uint32_t b1) {
    asm volatile("mma.sync.aligned.m16n8k16.row.col.f16.f16.f16.f16 "
                 "{%0,%1}, {%2,%3,%4,%5}, {%6,%7}, {%0,%1};"
                 : "+r"(c[0]), "+r"(c[1])
                 : "r"(a[0]), "r"(a[1]), "r"(a[2]), "r"(a[3]), "r"(b0), "r"(b1));
}
#define CP16(dst, src)  asm volatile("cp.async.cg.shared.global [%0], [%1], 16;" :: "r"(dst), "l"(src) : "memory")
#define CPCOMMIT()      asm volatile("cp.async.commit_group;" ::: "memory")
#define CPWAIT0()       asm volatile("cp.async.wait_group 0;" ::: "memory")

__device__ __forceinline__ unsigned long long pack_vi(float v, int idx) {
    return ((unsigned long long)__float_as_uint(v + 2.0f) << 32) |
           (unsigned)(8191 - idx);
}
__device__ __forceinline__ int unpack_idx(unsigned long long p) {
    return 8191 - (int)(p & 0xFFFFFFFFull);
}
__device__ __forceinline__ unsigned long long u64max(unsigned long long a,
                                                     unsigned long long b) {
    return a > b ? a : b;
}
__device__ __forceinline__ unsigned long long shfl_xor_u64(unsigned long long v, int m) {
    uint32_t lo = (uint32_t)v, hi = (uint32_t)(v >> 32);
    lo = __shfl_xor_sync(0xffffffffu, lo, m);
    hi = __shfl_xor_sync(0xffffffffu, hi, m);
    return ((unsigned long long)hi << 32) | lo;
}

// replay-safe grid barrier: generation counting, monotonic counter.
__device__ __forceinline__ void grid_bar(int w) {
    __threadfence();
    __syncthreads();
    if (threadIdx.x == 0) {
        unsigned old = atomicAdd(&g_barc[w], 1u);
        unsigned target = (old / NCTA + 1u) * NCTA;
        for (;;) {
            unsigned cur;
            asm volatile("ld.acquire.gpu.global.u32 %0, [%1];"
                         : "=r"(cur) : "l"(&g_barc[w]));
            if (cur >= target) break;
            asm volatile("nanosleep.u32 64;");
        }
    }
    __syncthreads();
    __threadfence();
}

// ---------------------------------------------------------------------------
// phase 2 building blocks (identical to R8's 16-warp config)
__device__ __forceinline__ void mma_tile(uint32_t (&c_)[2][4][2], uint32_t uA, uint32_t uB,
                                         uint32_t aoff, uint32_t boff,
                                         bool pf, uint32_t pfdst,
                                         const __half* __restrict__ pfsrc, int tid) {
    #pragma unroll
    for (int mi = 0; mi < 2; mi++)
        #pragma unroll
        for (int ni = 0; ni < 4; ni++) { c_[mi][ni][0] = 0u; c_[mi][ni][1] = 0u; }
    #pragma unroll
    for (int k = 0; k < 16; k++) {
        if (k >= 4 && k < 12 && pf) {
            int flat = tid + (k - 4) * NTHR;
            int r = flat >> 5;
            int c = flat & 31;
            CP16(pfdst + r * RSB + c * 16, pfsrc + (size_t)r * DIM + c * 8);
        }
        uint32_t a0[4], a1[4];
        ldsm4(a0, uA + aoff + k * 32);
        ldsm4(a1, uA + aoff + 16 * RSB + k * 32);
        uint32_t b[2][4];
        ldsm4(b[0], uB + boff + k * 32);
        ldsm4(b[1], uB + boff + 16 * RSB + k * 32);
        #pragma unroll
        for (int ni = 0; ni < 4; ni++) {
            uint32_t b0 = b[ni >> 1][(ni & 1) * 2];
            uint32_t b1 = b[ni >> 1][(ni & 1) * 2 + 1];
            mma16816h(c_[0][ni], a0, b0, b1);
            mma16816h(c_[1][ni], a1, b0, b1);
        }
    }
}

__device__ __forceinline__ void fold_tile(const uint32_t (&c_)[2][4][2], int pi, int pj,
                                          int rloc, int wn, int l,
                                          float best[4], int bidx[4]) {
    const int colb = pj * 128 + wn * 32 + (l & 3) * 2;
    const int rbase = pi * 128 + rloc;
    float f[2][4][4];
    #pragma unroll
    for (int mi = 0; mi < 2; mi++)
        #pragma unroll
        for (int ni = 0; ni < 4; ni++) {
            float2 lo = __half22float2(*(const __half2*)&c_[mi][ni][0]);
            float2 hi = __half22float2(*(const __half2*)&c_[mi][ni][1]);
            f[mi][ni][0] = lo.x; f[mi][ni][1] = lo.y;
            f[mi][ni][2] = hi.x; f[mi][ni][3] = hi.y;
        }
    if (pi == pj) {
        #pragma unroll
        for (int mi = 0; mi < 2; mi++)
            #pragma unroll
            for (int h = 0; h < 2; h++) {
                const int bi = mi * 2 + h;
                const int row = rbase + mi * 16 + h * 8;
                #pragma unroll
                for (int ni = 0; ni < 4; ni++)
                    #pragma unroll
                    for (int bb = 0; bb < 2; bb++) {
                        float v = f[mi][ni][h * 2 + bb];
                        int col = colb + ni * 8 + bb;
                        if (col == row) continue;
                        if (v > best[bi]) { best[bi] = v; bidx[bi] = col; }
                    }
            }
    } else {
        #pragma unroll
        for (int mi = 0; mi < 2; mi++)
            #pragma unroll
            for (int h = 0; h < 2; h++) {
                const int bi = mi * 2 + h;
                #pragma unroll
                for (int ni = 0; ni < 4; ni++)
                    #pragma unroll
                    for (int bb = 0; bb < 2; bb++) {
                        float v = f[mi][ni][h * 2 + bb];
                        int col = colb + ni * 8 + bb;
                        if (v > best[bi]) { best[bi] = v; bidx[bi] = col; }
                    }
            }
        #pragma unroll
        for (int ni = 0; ni < 4; ni++)
            #pragma unroll
            for (int bb = 0; bb < 2; bb++) {
                float bv = f[0][ni][bb];       int br = rbase;
                float v;
                v = f[0][ni][2 + bb]; if (v > bv) { bv = v; br = rbase + 8;  }
                v = f[1][ni][bb];     if (v > bv) { bv = v; br = rbase + 16; }
                v = f[1][ni][2 + bb]; if (v > bv) { bv = v; br = rbase + 24; }
                unsigned long long p = pack_vi(bv, br);
                p = u64max(p, shfl_xor_u64(p, 4));
                p = u64max(p, shfl_xor_u64(p, 8));
                p = u64max(p, shfl_xor_u64(p, 16));
                if ((l >> 2) == 0)
                    atomicMax(&g_best[colb + ni * 8 + bb], p);
            }
    }
}

__device__ __forceinline__ void flush_rows(int rowblk, int rloc, int l,
                                           float best[4], int bidx[4]) {
    #pragma unroll
    for (int bi = 0; bi < 4; bi++) {
        unsigned long long p = pack_vi(best[bi], bidx[bi]);
        p = u64max(p, shfl_xor_u64(p, 1));
        p = u64max(p, shfl_xor_u64(p, 2));
        if ((l & 3) == 0) {
            int row = rowblk * 128 + rloc + (bi >> 1) * 16 + (bi & 1) * 8;
            atomicMax(&g_best[row], p);
        }
        best[bi] = -2.0f; bidx[bi] = 0;
    }
}

__device__ __forceinline__ int free_slot(int sa, int sb) {
    if (sa != 0 && sb != 0) return 0;
    if (sa != 1 && sb != 1) return 1;
    return 2;
}

// ---------------------------------------------------------------------------
// ONE persistent kernel: normalize -> barrier -> gemm-argmax -> barrier -> loss
__global__ void __launch_bounds__(NTHR, 1) koleo_all(const float* __restrict__ x,
                                                     float* __restrict__ out) {
    extern __shared__ __align__(16) char smem[];
    __shared__ float s_part[NWARP];
    const uint32_t su = smem_u32(smem);
    const int tid = threadIdx.x;
    const int l   = tid & 31;
    const int wid = tid >> 5;
    const int b   = blockIdx.x;
    const int gw  = b * NWARP + wid;          // global warp id

    // ---------------- phase 1: normalize + fp16 convert --------------------
    if (b == 0 && tid == 0) out[0] = 0.0f;
    for (int row = gw; row < BROWS; row += TOTW) {
        const float4* src = (const float4*)(x + (size_t)row * DIM);
        float4 v0 = src[l];
        float4 v1 = src[l + 32];
        float s = v0.x*v0.x + v0.y*v0.y + v0.z*v0.z + v0.w*v0.w
                + v1.x*v1.x + v1.y*v1.y + v1.z*v1.z + v1.w*v1.w;
        #pragma unroll
        for (int o = 16; o > 0; o >>= 1) s += __shfl_xor_sync(0xffffffffu, s, o);
        float inv = 1.0f / fmaxf(sqrtf(s), kEPS);
        v0.x *= inv; v0.y *= inv; v0.z *= inv; v0.w *= inv;
        v1.x *= inv; v1.y *= inv; v1.z *= inv; v1.w *= inv;
        ushort4 H0, H1;
        H0.x = __half_as_ushort(__float2half_rn(v0.x));
        H0.y = __half_as_ushort(__float2half_rn(v0.y));
        H0.z = __half_as_ushort(__float2half_rn(v0.z));
        H0.w = __half_as_ushort(__float2half_rn(v0.w));
        H1.x = __half_as_ushort(__float2half_rn(v1.x));
        H1.y = __half_as_ushort(__float2half_rn(v1.y));
        H1.z = __half_as_ushort(__float2half_rn(v1.z));
        H1.w = __half_as_ushort(__float2half_rn(v1.w));
        ushort4* hdst = (ushort4*)(g_xh + (size_t)row * DIM);
        hdst[l] = H0; hdst[l + 32] = H1;
        if (l == 0) { g_inv[row] = inv; g_best[row] = 0ull; }
    }

    grid_bar(0);

    // ---------------- phase 2: persistent upper-tri GEMM-argmax ------------
    {
        const int wm  = wid >> 2;
        const int wn  = wid & 3;
        const int rloc = wm * 32 + (l >> 2);

        const int cnt = 14 + (b < 8 ? 1 : 0);
        int s = b * 14 + (b < 8 ? b : 8);
        int i = 0;
        while (s >= 64 - i) { s -= 64 - i; i++; }
        int j = i + s;

        const uint32_t aoff = (uint32_t)((wm * 32 + (l & 15)) * RSB + (l >> 4) * 16);
        const uint32_t boff = (uint32_t)((wn * 32 + (l & 7) + ((l >> 4) << 3)) * RSB +
                                         ((l >> 3) & 1) * 16);

        int sa = 0, sb;
        #pragma unroll
        for (int q = 0; q < 8; q++) {
            int flat = tid + q * NTHR;
            int r = flat >> 5;
            int c = flat & 31;
            CP16(su + r * RSB + c * 16,
                 g_xh + (size_t)i * 128 * DIM + (size_t)r * DIM + c * 8);
        }
        if (j != i) {
            #pragma unroll
            for (int q = 0; q < 8; q++) {
                int flat = tid + q * NTHR;
                int r = flat >> 5;
                int c = flat & 31;
                CP16(su + ATILE + r * RSB + c * 16,
                     g_xh + (size_t)j * 128 * DIM + (size_t)r * DIM + c * 8);
            }
            sb = 1;
        } else sb = 0;
        CPCOMMIT();

        float best[4] = {-2.0f, -2.0f, -2.0f, -2.0f};
        int   bidx[4] = {0, 0, 0, 0};
        uint32_t c_[2][4][2];

        #pragma unroll 1
        for (int n = 0; n < cnt; n++) {
            CPWAIT0();
            __syncthreads();

            int nsa = sa, nsb = sb, ii2 = i, jj2 = j;
            bool pf = (n + 1 < cnt);
            uint32_t pfdst = 0;
            const __half* pfsrc = nullptr;
            if (pf) {
                int fs = free_slot(sa, sb);
                pfdst = su + fs * ATILE;
                if (j + 1 < 64) {
                    pfsrc = g_xh + (size_t)(j + 1) * 128 * DIM;
                    nsb = fs; jj2 = j + 1;
                } else {
                    pfsrc = g_xh + (size_t)(i + 1) * 128 * DIM;
                    nsa = fs; nsb = fs; ii2 = i + 1; jj2 = i + 1;
                }
            }

            mma_tile(c_, su + sa * ATILE, su + sb * ATILE, aoff, boff, pf, pfdst, pfsrc, tid);
            if (pf) CPCOMMIT();
            fold_tile(c_, i, j, rloc, wn, l, best, bidx);
            if (n + 1 == cnt || ii2 != i)
                flush_rows(i, rloc, l, best, bidx);

            sa = nsa; sb = nsb; i = ii2; j = jj2;
        }
    }

    grid_bar(1);

    // ---------------- phase 3: distances + loss reduction ------------------
    {
        float acc = 0.0f;
        for (int row = gw; row < BROWS; row += TOTW) {
            unsigned long long pb;
            asm volatile("ld.global.cg.u64 %0, [%1];" : "=l"(pb) : "l"(g_best + row));
            int nb = unpack_idx(pb);
            float ii, ij;
            asm volatile("ld.global.cg.f32 %0, [%1];" : "=f"(ii) : "l"(g_inv + row));
            asm volatile("ld.global.cg.f32 %0, [%1];" : "=f"(ij) : "l"(g_inv + nb));
            const float4* xi = (const float4*)(x + (size_t)row * DIM);
            const float4* xj = (const float4*)(x + (size_t)nb  * DIM);
            float s = 0.0f;
            #pragma unroll
            for (int c = 0; c < 2; c++) {
                float4 a = xi[l + c * 32];
                float4 bb = xj[l + c * 32];
                float d0 = a.x * ii - bb.x * ij + kEPS, d1 = a.y * ii - bb.y * ij + kEPS;
                float d2 = a.z * ii - bb.z * ij + kEPS, d3 = a.w * ii - bb.w * ij + kEPS;
                s = fmaf(d0, d0, s); s = fmaf(d1, d1, s);
                s = fmaf(d2, d2, s); s = fmaf(d3, d3, s);
            }
            #pragma unroll
            for (int o = 16; o > 0; o >>= 1) s += __shfl_xor_sync(0xffffffffu, s, o);
            if (l == 0) acc += logf(sqrtf(s) + kEPS);
        }
        if (l == 0) s_part[wid] = acc;
        __syncthreads();
        if (tid == 0) {
            float t = 0.0f;
            #pragma unroll
            for (int w = 0; w < NWARP; w++) t += s_part[w];
            atomicAdd(out, t * (-1.0f / (float)BROWS));
        }
    }
}

// ---------------------------------------------------------------------------
extern "C" void kernel_launch(void* const* d_in, const int* in_sizes, int n_in,
                              void* d_out, int out_size) {
    const float* student = (const float*)d_in[0];
    float* out = (float*)d_out;
    (void)in_sizes; (void)n_in; (void)out_size;

    const int smem_bytes = 3 * ATILE;      // 202752 B dynamic
    cudaFuncSetAttribute(koleo_all, cudaFuncAttributeMaxDynamicSharedMemorySize, smem_bytes);
    koleo_all<<<NCTA, NTHR, smem_bytes>>>(student, out);
}

// round 11
// speedup vs baseline: 1.0603x; 1.0603x over previous
#include <cuda_runtime.h>
#include <cuda_fp16.h>
#include <math.h>
#include <stdint.h>

#define BROWS 8192
#define DIM   256
#define RSB   528           // smem row stride bytes (256 halves + 8 pad)
#define ATILE (128 * RSB)   // 67584 B per tile slot
#define NCTA  148
#define NTHR  512

static __device__ __constant__ float kEPS = 1e-8f;

// ------------------------- device scratch ----------------------------------
__device__ __align__(16) __half g_xh[BROWS * DIM];   // normalized fp16 (4 MB)
__device__ float                g_inv[BROWS];        // per-row 1/norm
__device__ unsigned long long   g_best[BROWS];

// ------------------------- helpers -----------------------------------------
__device__ __forceinline__ uint32_t smem_u32(const void* p) {
    uint32_t a;
    asm("{ .reg .u64 t; cvta.to.shared.u64 t, %1; cvt.u32.u64 %0, t; }" : "=r"(a) : "l"(p));
    return a;
}
__device__ __forceinline__ void ldsm4(uint32_t r[4], uint32_t a) {
    asm volatile("ldmatrix.sync.aligned.m8n8.x4.shared.b16 {%0,%1,%2,%3}, [%4];"
                 : "=r"(r[0]), "=r"(r[1]), "=r"(r[2]), "=r"(r[3]) : "r"(a));
}
__device__ __forceinline__ void mma16816h(uint32_t c[2], const uint32_t a[4],
                                          uint32_t b0, uint32_t b1) {
    asm volatile("mma.sync.aligned.m16n8k16.row.col.f16.f16.f16.f16 "
                 "{%0,%1}, {%2,%3,%4,%5}, {%6,%7}, {%0,%1};"
                 : "+r"(c[0]), "+r"(c[1])
                 : "r"(a[0]), "r"(a[1]), "r"(a[2]), "r"(a[3]), "r"(b0), "r"(b1));
}
#define CP16(dst, src)  asm volatile("cp.async.cg.shared.global [%0], [%1], 16;" :: "r"(dst), "l"(src) : "memory")
#define CPCOMMIT()      asm volatile("cp.async.commit_group;" ::: "memory")
#define CPWAIT0()       asm volatile("cp.async.wait_group 0;" ::: "memory")

__device__ __forceinline__ unsigned long long pack_vi(float v, int idx) {
    return ((unsigned long long)__float_as_uint(v + 2.0f) << 32) |
           (unsigned)(8191 - idx);
}
__device__ __forceinline__ int unpack_idx(unsigned long long p) {
    return 8191 - (int)(p & 0xFFFFFFFFull);
}
__device__ __forceinline__ unsigned long long u64max(unsigned long long a,
                                                     unsigned long long b) {
    return a > b ? a : b;
}
__device__ __forceinline__ unsigned long long shfl_xor_u64(unsigned long long v, int m) {
    uint32_t lo = (uint32_t)v, hi = (uint32_t)(v >> 32);
    lo = __shfl_xor_sync(0xffffffffu, lo, m);
    hi = __shfl_xor_sync(0xffffffffu, hi, m);
    return ((unsigned long long)hi << 32) | lo;
}

// ---------------------------------------------------------------------------
// Kernel 1: normalize -> fp16 + inv-norm; zero g_best; zero out. 1 warp/row.
__global__ void koleo_normcvt(const float* __restrict__ x, float* __restrict__ out) {
    int row  = blockIdx.x * 8 + (threadIdx.x >> 5);
    int lane = threadIdx.x & 31;
    const float4* src = (const float4*)(x + (size_t)row * DIM);
    float4 v0 = src[lane];
    float4 v1 = src[lane + 32];
    float s = v0.x*v0.x + v0.y*v0.y + v0.z*v0.z + v0.w*v0.w
            + v1.x*v1.x + v1.y*v1.y + v1.z*v1.z + v1.w*v1.w;
    #pragma unroll
    for (int o = 16; o > 0; o >>= 1) s += __shfl_xor_sync(0xffffffffu, s, o);
    float inv = 1.0f / fmaxf(sqrtf(s), kEPS);
    v0.x *= inv; v0.y *= inv; v0.z *= inv; v0.w *= inv;
    v1.x *= inv; v1.y *= inv; v1.z *= inv; v1.w *= inv;

    ushort4 H0, H1;
    H0.x = __half_as_ushort(__float2half_rn(v0.x));
    H0.y = __half_as_ushort(__float2half_rn(v0.y));
    H0.z = __half_as_ushort(__float2half_rn(v0.z));
    H0.w = __half_as_ushort(__float2half_rn(v0.w));
    H1.x = __half_as_ushort(__float2half_rn(v1.x));
    H1.y = __half_as_ushort(__float2half_rn(v1.y));
    H1.z = __half_as_ushort(__float2half_rn(v1.z));
    H1.w = __half_as_ushort(__float2half_rn(v1.w));
    ushort4* hdst = (ushort4*)(g_xh + (size_t)row * DIM);
    hdst[lane] = H0; hdst[lane + 32] = H1;
    if (lane == 0) { g_inv[row] = inv; g_best[row] = 0ull; }
    if (blockIdx.x == 0 && threadIdx.x == 0) out[0] = 0.0f;
}

// ---------------------------------------------------------------------------
// 32x32 warp tile, fp16 acc, SOFTWARE-PIPELINED fragments: ldsm for k+1
// issues before HMMAs of k, so HMMA never waits on a fresh ldsm.
// Next-tile cp.async prefetch interleaved at k=4..11.
__device__ __forceinline__ void mma_tile(uint32_t (&c_)[2][4][2], uint32_t uA, uint32_t uB,
                                         uint32_t aoff, uint32_t boff,
                                         bool pf, uint32_t pfdst,
                                         const __half* __restrict__ pfsrc, int tid) {
    #pragma unroll
    for (int mi = 0; mi < 2; mi++)
        #pragma unroll
        for (int ni = 0; ni < 4; ni++) { c_[mi][ni][0] = 0u; c_[mi][ni][1] = 0u; }

    uint32_t a0[2][4], a1[2][4], bf[2][2][4];
    ldsm4(a0[0], uA + aoff);
    ldsm4(a1[0], uA + aoff + 16 * RSB);
    ldsm4(bf[0][0], uB + boff);
    ldsm4(bf[0][1], uB + boff + 16 * RSB);

    #pragma unroll
    for (int k = 0; k < 16; k++) {
        const int cur = k & 1, nxt = cur ^ 1;
        if (k < 15) {
            ldsm4(a0[nxt], uA + aoff + (k + 1) * 32);
            ldsm4(a1[nxt], uA + aoff + 16 * RSB + (k + 1) * 32);
            ldsm4(bf[nxt][0], uB + boff + (k + 1) * 32);
            ldsm4(bf[nxt][1], uB + boff + 16 * RSB + (k + 1) * 32);
        }
        if (k >= 4 && k < 12 && pf) {
            int flat = tid + (k - 4) * NTHR;
            int r = flat >> 5;
            int c = flat & 31;
            CP16(pfdst + r * RSB + c * 16, pfsrc + (size_t)r * DIM + c * 8);
        }
        #pragma unroll
        for (int ni = 0; ni < 4; ni++) {
            uint32_t b0 = bf[cur][ni >> 1][(ni & 1) * 2];
            uint32_t b1 = bf[cur][ni >> 1][(ni & 1) * 2 + 1];
            mma16816h(c_[0][ni], a0[cur], b0, b1);
            mma16816h(c_[1][ni], a1[cur], b0, b1);
        }
    }
}

// fold tile (pi, pj): row-side into running best, column-side via REDG.
__device__ __forceinline__ void fold_tile(const uint32_t (&c_)[2][4][2], int pi, int pj,
                                          int rloc, int wn, int l,
                                          float best[4], int bidx[4]) {
    const int colb = pj * 128 + wn * 32 + (l & 3) * 2;
    const int rbase = pi * 128 + rloc;
    float f[2][4][4];
    #pragma unroll
    for (int mi = 0; mi < 2; mi++)
        #pragma unroll
        for (int ni = 0; ni < 4; ni++) {
            float2 lo = __half22float2(*(const __half2*)&c_[mi][ni][0]);
            float2 hi = __half22float2(*(const __half2*)&c_[mi][ni][1]);
            f[mi][ni][0] = lo.x; f[mi][ni][1] = lo.y;
            f[mi][ni][2] = hi.x; f[mi][ni][3] = hi.y;
        }
    if (pi == pj) {
        #pragma unroll
        for (int mi = 0; mi < 2; mi++)
            #pragma unroll
            for (int h = 0; h < 2; h++) {
                const int bi = mi * 2 + h;
                const int row = rbase + mi * 16 + h * 8;
                #pragma unroll
                for (int ni = 0; ni < 4; ni++)
                    #pragma unroll
                    for (int bb = 0; bb < 2; bb++) {
                        float v = f[mi][ni][h * 2 + bb];
                        int col = colb + ni * 8 + bb;
                        if (col == row) continue;
                        if (v > best[bi]) { best[bi] = v; bidx[bi] = col; }
                    }
            }
    } else {
        #pragma unroll
        for (int mi = 0; mi < 2; mi++)
            #pragma unroll
            for (int h = 0; h < 2; h++) {
                const int bi = mi * 2 + h;
                #pragma unroll
                for (int ni = 0; ni < 4; ni++)
                    #pragma unroll
                    for (int bb = 0; bb < 2; bb++) {
                        float v = f[mi][ni][h * 2 + bb];
                        int col = colb + ni * 8 + bb;
                        if (v > best[bi]) { best[bi] = v; bidx[bi] = col; }
                    }
            }
        #pragma unroll
        for (int ni = 0; ni < 4; ni++)
            #pragma unroll
            for (int bb = 0; bb < 2; bb++) {
                float bv = f[0][ni][bb];       int br = rbase;
                float v;
                v = f[0][ni][2 + bb]; if (v > bv) { bv = v; br = rbase + 8;  }
                v = f[1][ni][bb];     if (v > bv) { bv = v; br = rbase + 16; }
                v = f[1][ni][2 + bb]; if (v > bv) { bv = v; br = rbase + 24; }
                unsigned long long p = pack_vi(bv, br);
                p = u64max(p, shfl_xor_u64(p, 4));
                p = u64max(p, shfl_xor_u64(p, 8));
                p = u64max(p, shfl_xor_u64(p, 16));
                if ((l >> 2) == 0)
                    atomicMax(&g_best[colb + ni * 8 + bb], p);
            }
    }
}

__device__ __forceinline__ void flush_rows(int rowblk, int rloc, int l,
                                           float best[4], int bidx[4]) {
    #pragma unroll
    for (int bi = 0; bi < 4; bi++) {
        unsigned long long p = pack_vi(best[bi], bidx[bi]);
        p = u64max(p, shfl_xor_u64(p, 1));
        p = u64max(p, shfl_xor_u64(p, 2));
        if ((l & 3) == 0) {
            int row = rowblk * 128 + rloc + (bi >> 1) * 16 + (bi & 1) * 8;
            atomicMax(&g_best[row], p);
        }
        best[bi] = -2.0f; bidx[bi] = 0;
    }
}

__device__ __forceinline__ int free_slot(int sa, int sb) {
    if (sa != 0 && sb != 0) return 0;
    if (sa != 1 && sb != 1) return 1;
    return 2;
}

// ---------------------------------------------------------------------------
// Kernel 2: persistent balanced upper-tri GEMM-argmax. 148 CTAs, 512 thr,
// 16 warps (4x4 grid of 32x32 warp tiles), pipelined fragments.
__global__ void __launch_bounds__(NTHR, 1) koleo_gemm() {
    extern __shared__ __align__(16) char smem[];
    const uint32_t su = smem_u32(smem);
    const int tid = threadIdx.x;
    const int l   = tid & 31;
    const int wid = tid >> 5;
    const int wm  = wid >> 2;            // 0..3 (M)
    const int wn  = wid & 3;             // 0..3 (N)
    const int rloc = wm * 32 + (l >> 2);
    const int b   = blockIdx.x;

    const int cnt = 14 + (b < 8 ? 1 : 0);
    int s = b * 14 + (b < 8 ? b : 8);
    int i = 0;
    while (s >= 64 - i) { s -= 64 - i; i++; }
    int j = i + s;

    const uint32_t aoff = (uint32_t)((wm * 32 + (l & 15)) * RSB + (l >> 4) * 16);
    const uint32_t boff = (uint32_t)((wn * 32 + (l & 7) + ((l >> 4) << 3)) * RSB +
                                     ((l >> 3) & 1) * 16);

    // initial loads (full tiles)
    int sa = 0, sb;
    #pragma unroll
    for (int q = 0; q < 8; q++) {
        int flat = tid + q * NTHR;
        int r = flat >> 5;
        int c = flat & 31;
        CP16(su + r * RSB + c * 16, g_xh + (size_t)i * 128 * DIM + (size_t)r * DIM + c * 8);
    }
    if (j != i) {
        #pragma unroll
        for (int q = 0; q < 8; q++) {
            int flat = tid + q * NTHR;
            int r = flat >> 5;
            int c = flat & 31;
            CP16(su + ATILE + r * RSB + c * 16,
                 g_xh + (size_t)j * 128 * DIM + (size_t)r * DIM + c * 8);
        }
        sb = 1;
    } else sb = 0;
    CPCOMMIT();

    float best[4] = {-2.0f, -2.0f, -2.0f, -2.0f};
    int   bidx[4] = {0, 0, 0, 0};
    uint32_t c_[2][4][2];

    #pragma unroll 1
    for (int n = 0; n < cnt; n++) {
        CPWAIT0();
        __syncthreads();

        int nsa = sa, nsb = sb, ii2 = i, jj2 = j;
        bool pf = (n + 1 < cnt);
        uint32_t pfdst = 0;
        const __half* pfsrc = nullptr;
        if (pf) {
            int fs = free_slot(sa, sb);
            pfdst = su + fs * ATILE;
            if (j + 1 < 64) {
                pfsrc = g_xh + (size_t)(j + 1) * 128 * DIM;
                nsb = fs; jj2 = j + 1;
            } else {
                pfsrc = g_xh + (size_t)(i + 1) * 128 * DIM;
                nsa = fs; nsb = fs; ii2 = i + 1; jj2 = i + 1;
            }
        }

        mma_tile(c_, su + sa * ATILE, su + sb * ATILE, aoff, boff, pf, pfdst, pfsrc, tid);
        if (pf) CPCOMMIT();
        fold_tile(c_, i, j, rloc, wn, l, best, bidx);
        if (n + 1 == cnt || ii2 != i)
            flush_rows(i, rloc, l, best, bidx);

        sa = nsa; sb = nsb; i = ii2; j = jj2;
    }
}

// ---------------------------------------------------------------------------
// Kernel 3: per-row distance + log + fused reduction. One warp per row.
__global__ void koleo_dist(const float* __restrict__ x, float* __restrict__ out) {
    __shared__ float sh[8];
    int row  = blockIdx.x * 8 + (threadIdx.x >> 5);
    int lane = threadIdx.x & 31;
    int nb   = unpack_idx(g_best[row]);
    float ii = g_inv[row];
    float ij = g_inv[nb];
    const float4* xi = (const float4*)(x + (size_t)row * DIM);
    const float4* xj = (const float4*)(x + (size_t)nb  * DIM);
    float s = 0.0f;
    #pragma unroll
    for (int c = 0; c < 2; c++) {
        float4 a = xi[lane + c * 32];
        float4 b = xj[lane + c * 32];
        float d0 = a.x * ii - b.x * ij + kEPS, d1 = a.y * ii - b.y * ij + kEPS;
        float d2 = a.z * ii - b.z * ij + kEPS, d3 = a.w * ii - b.w * ij + kEPS;
        s = fmaf(d0, d0, s); s = fmaf(d1, d1, s);
        s = fmaf(d2, d2, s); s = fmaf(d3, d3, s);
    }
    #pragma unroll
    for (int o = 16; o > 0; o >>= 1) s += __shfl_xor_sync(0xffffffffu, s, o);
    if (lane == 0) sh[threadIdx.x >> 5] = logf(sqrtf(s) + kEPS);
    __syncthreads();
    if (threadIdx.x == 0) {
        float t = sh[0] + sh[1] + sh[2] + sh[3] + sh[4] + sh[5] + sh[6] + sh[7];
        atomicAdd(out, t * (-1.0f / (float)BROWS));
    }
}

// ---------------------------------------------------------------------------
extern "C" void kernel_launch(void* const* d_in, const int* in_sizes, int n_in,
                              void* d_out, int out_size) {
    const float* student = (const float*)d_in[0];
    float* out = (float*)d_out;
    (void)in_sizes; (void)n_in; (void)out_size;

    const int smem_bytes = 3 * ATILE;      // 202752 B dynamic
    cudaFuncSetAttribute(koleo_gemm, cudaFuncAttributeMaxDynamicSharedMemorySize, smem_bytes);

    koleo_normcvt<<<BROWS / 8, 256>>>(student, out);
    koleo_gemm<<<NCTA, NTHR, smem_bytes>>>();
    koleo_dist<<<BROWS / 8, 256>>>(student, out);
}

// round 12
// speedup vs baseline: 1.0617x; 1.0013x over previous
#include <cuda_runtime.h>
#include <cuda_fp16.h>
#include <math.h>
#include <stdint.h>

#define BROWS 8192
#define DIM   256
#define RSB   528               // smem row stride bytes (256 halves + 8 pad)
#define ATILE (128 * RSB)       // 67584 B: shared A slot
#define BTILE (64 * RSB)        // 33792 B: per-team B slot (64 rows)
#define NCTA  148
#define NTHR  512

static __device__ __constant__ float kEPS = 1e-8f;

// ------------------------- device scratch ----------------------------------
__device__ __align__(16) __half g_xh[BROWS * DIM];
__device__ float                g_inv[BROWS];
__device__ unsigned long long   g_best[BROWS];

// ------------------------- helpers -----------------------------------------
__device__ __forceinline__ uint32_t smem_u32(const void* p) {
    uint32_t a;
    asm("{ .reg .u64 t; cvta.to.shared.u64 t, %1; cvt.u32.u64 %0, t; }" : "=r"(a) : "l"(p));
    return a;
}
__device__ __forceinline__ void ldsm4(uint32_t r[4], uint32_t a) {
    asm volatile("ldmatrix.sync.aligned.m8n8.x4.shared.b16 {%0,%1,%2,%3}, [%4];"
                 : "=r"(r[0]), "=r"(r[1]), "=r"(r[2]), "=r"(r[3]) : "r"(a));
}
__device__ __forceinline__ void mma16816h(uint32_t c[2], const uint32_t a[4],
                                          uint32_t b0, uint32_t b1) {
    asm volatile("mma.sync.aligned.m16n8k16.row.col.f16.f16.f16.f16 "
                 "{%0,%1}, {%2,%3,%4,%5}, {%6,%7}, {%0,%1};"
                 : "+r"(c[0]), "+r"(c[1])
                 : "r"(a[0]), "r"(a[1]), "r"(a[2]), "r"(a[3]), "r"(b0), "r"(b1));
}
#define CP16(dst, src)  asm volatile("cp.async.cg.shared.global [%0], [%1], 16;" :: "r"(dst), "l"(src) : "memory")
#define CPCOMMIT()      asm volatile("cp.async.commit_group;" ::: "memory")
#define CPWAIT0()       asm volatile("cp.async.wait_group 0;" ::: "memory")
#define TEAMBAR(t)      asm volatile("bar.sync %0, 256;" :: "r"((t) + 1) : "memory")

__device__ __forceinline__ unsigned long long pack_vi(float v, int idx) {
    return ((unsigned long long)__float_as_uint(v + 2.0f) << 32) |
           (unsigned)(8191 - idx);
}
__device__ __forceinline__ int unpack_idx(unsigned long long p) {
    return 8191 - (int)(p & 0xFFFFFFFFull);
}
__device__ __forceinline__ unsigned long long u64max(unsigned long long a,
                                                     unsigned long long b) {
    return a > b ? a : b;
}
__device__ __forceinline__ unsigned long long shfl_xor_u64(unsigned long long v, int m) {
    uint32_t lo = (uint32_t)v, hi = (uint32_t)(v >> 32);
    lo = __shfl_xor_sync(0xffffffffu, lo, m);
    hi = __shfl_xor_sync(0xffffffffu, hi, m);
    return ((unsigned long long)hi << 32) | lo;
}

// ---------------------------------------------------------------------------
// Kernel 1: normalize -> fp16 + inv-norm. 2 rows per warp for MLP.
__global__ void koleo_normcvt(const float* __restrict__ x, float* __restrict__ out) {
    int wid  = threadIdx.x >> 5;
    int lane = threadIdx.x & 31;
    int r0 = blockIdx.x * 16 + wid * 2;
    int r1 = r0 + 1;
    const float4* s0 = (const float4*)(x + (size_t)r0 * DIM);
    const float4* s1 = (const float4*)(x + (size_t)r1 * DIM);
    float4 a0 = s0[lane], a1 = s0[lane + 32];
    float4 b0 = s1[lane], b1 = s1[lane + 32];
    float sa = a0.x*a0.x + a0.y*a0.y + a0.z*a0.z + a0.w*a0.w
             + a1.x*a1.x + a1.y*a1.y + a1.z*a1.z + a1.w*a1.w;
    float sb = b0.x*b0.x + b0.y*b0.y + b0.z*b0.z + b0.w*b0.w
             + b1.x*b1.x + b1.y*b1.y + b1.z*b1.z + b1.w*b1.w;
    #pragma unroll
    for (int o = 16; o > 0; o >>= 1) {
        sa += __shfl_xor_sync(0xffffffffu, sa, o);
        sb += __shfl_xor_sync(0xffffffffu, sb, o);
    }
    float ia = 1.0f / fmaxf(sqrtf(sa), kEPS);
    float ib = 1.0f / fmaxf(sqrtf(sb), kEPS);

    ushort4 H;
    ushort4* d0 = (ushort4*)(g_xh + (size_t)r0 * DIM);
    ushort4* d1 = (ushort4*)(g_xh + (size_t)r1 * DIM);
    H.x = __half_as_ushort(__float2half_rn(a0.x * ia));
    H.y = __half_as_ushort(__float2half_rn(a0.y * ia));
    H.z = __half_as_ushort(__float2half_rn(a0.z * ia));
    H.w = __half_as_ushort(__float2half_rn(a0.w * ia));
    d0[lane] = H;
    H.x = __half_as_ushort(__float2half_rn(a1.x * ia));
    H.y = __half_as_ushort(__float2half_rn(a1.y * ia));
    H.z = __half_as_ushort(__float2half_rn(a1.z * ia));
    H.w = __half_as_ushort(__float2half_rn(a1.w * ia));
    d0[lane + 32] = H;
    H.x = __half_as_ushort(__float2half_rn(b0.x * ib));
    H.y = __half_as_ushort(__float2half_rn(b0.y * ib));
    H.z = __half_as_ushort(__float2half_rn(b0.z * ib));
    H.w = __half_as_ushort(__float2half_rn(b0.w * ib));
    d1[lane] = H;
    H.x = __half_as_ushort(__float2half_rn(b1.x * ib));
    H.y = __half_as_ushort(__float2half_rn(b1.y * ib));
    H.z = __half_as_ushort(__float2half_rn(b1.z * ib));
    H.w = __half_as_ushort(__float2half_rn(b1.w * ib));
    d1[lane + 32] = H;
    if (lane == 0) {
        g_inv[r0] = ia; g_best[r0] = 0ull;
        g_inv[r1] = ib; g_best[r1] = 0ull;
    }
    if (blockIdx.x == 0 && threadIdx.x == 0) out[0] = 0.0f;
}

// ---------------------------------------------------------------------------
// 32x32 warp tile, fp16 acc, pipelined fragments; team-B prefetch at k=4..11.
__device__ __forceinline__ void mma_tile(uint32_t (&c_)[2][4][2], uint32_t uA, uint32_t uB,
                                         uint32_t aoff, uint32_t boff,
                                         bool pf, uint32_t pfdst,
                                         const __half* __restrict__ pfsrc, int teamtid) {
    #pragma unroll
    for (int mi = 0; mi < 2; mi++)
        #pragma unroll
        for (int ni = 0; ni < 4; ni++) { c_[mi][ni][0] = 0u; c_[mi][ni][1] = 0u; }

    uint32_t a0[2][4], a1[2][4], bf[2][2][4];
    ldsm4(a0[0], uA + aoff);
    ldsm4(a1[0], uA + aoff + 16 * RSB);
    ldsm4(bf[0][0], uB + boff);
    ldsm4(bf[0][1], uB + boff + 16 * RSB);

    #pragma unroll
    for (int k = 0; k < 16; k++) {
        const int cur = k & 1, nxt = cur ^ 1;
        if (k < 15) {
            ldsm4(a0[nxt], uA + aoff + (k + 1) * 32);
            ldsm4(a1[nxt], uA + aoff + 16 * RSB + (k + 1) * 32);
            ldsm4(bf[nxt][0], uB + boff + (k + 1) * 32);
            ldsm4(bf[nxt][1], uB + boff + 16 * RSB + (k + 1) * 32);
        }
        if (k >= 4 && k < 12 && pf) {
            int flat = teamtid + (k - 4) * 256;
            int r = flat >> 5;
            int c = flat & 31;
            CP16(pfdst + r * RSB + c * 16, pfsrc + (size_t)r * DIM + c * 8);
        }
        #pragma unroll
        for (int ni = 0; ni < 4; ni++) {
            uint32_t b0 = bf[cur][ni >> 1][(ni & 1) * 2];
            uint32_t b1 = bf[cur][ni >> 1][(ni & 1) * 2 + 1];
            mma16816h(c_[0][ni], a0[cur], b0, b1);
            mma16816h(c_[1][ni], a1[cur], b0, b1);
        }
    }
}

// fold: row-side into running best, column-side via REDG atomics.
__device__ __forceinline__ void fold_tile(const uint32_t (&c_)[2][4][2],
                                          int rbase, int colb, bool diag, int l,
                                          float best[4], int bidx[4]) {
    float f[2][4][4];
    #pragma unroll
    for (int mi = 0; mi < 2; mi++)
        #pragma unroll
        for (int ni = 0; ni < 4; ni++) {
            float2 lo = __half22float2(*(const __half2*)&c_[mi][ni][0]);
            float2 hi = __half22float2(*(const __half2*)&c_[mi][ni][1]);
            f[mi][ni][0] = lo.x; f[mi][ni][1] = lo.y;
            f[mi][ni][2] = hi.x; f[mi][ni][3] = hi.y;
        }
    if (diag) {
        #pragma unroll
        for (int mi = 0; mi < 2; mi++)
            #pragma unroll
            for (int h = 0; h < 2; h++) {
                const int bi = mi * 2 + h;
                const int row = rbase + mi * 16 + h * 8;
                #pragma unroll
                for (int ni = 0; ni < 4; ni++)
                    #pragma unroll
                    for (int bb = 0; bb < 2; bb++) {
                        float v = f[mi][ni][h * 2 + bb];
                        int col = colb + ni * 8 + bb;
                        if (col == row) continue;
                        if (v > best[bi]) { best[bi] = v; bidx[bi] = col; }
                    }
            }
    } else {
        #pragma unroll
        for (int mi = 0; mi < 2; mi++)
            #pragma unroll
            for (int h = 0; h < 2; h++) {
                const int bi = mi * 2 + h;
                #pragma unroll
                for (int ni = 0; ni < 4; ni++)
                    #pragma unroll
                    for (int bb = 0; bb < 2; bb++) {
                        float v = f[mi][ni][h * 2 + bb];
                        int col = colb + ni * 8 + bb;
                        if (v > best[bi]) { best[bi] = v; bidx[bi] = col; }
                    }
            }
        #pragma unroll
        for (int ni = 0; ni < 4; ni++)
            #pragma unroll
            for (int bb = 0; bb < 2; bb++) {
                float bv = f[0][ni][bb];       int br = rbase;
                float v;
                v = f[0][ni][2 + bb]; if (v > bv) { bv = v; br = rbase + 8;  }
                v = f[1][ni][bb];     if (v > bv) { bv = v; br = rbase + 16; }
                v = f[1][ni][2 + bb]; if (v > bv) { bv = v; br = rbase + 24; }
                unsigned long long p = pack_vi(bv, br);
                p = u64max(p, shfl_xor_u64(p, 4));
                p = u64max(p, shfl_xor_u64(p, 8));
                p = u64max(p, shfl_xor_u64(p, 16));
                if ((l >> 2) == 0)
                    atomicMax(&g_best[colb + ni * 8 + bb], p);
            }
    }
}

__device__ __forceinline__ void flush_rows(int rowblk, int rloc, int l,
                                           float best[4], int bidx[4]) {
    #pragma unroll
    for (int bi = 0; bi < 4; bi++) {
        unsigned long long p = pack_vi(best[bi], bidx[bi]);
        p = u64max(p, shfl_xor_u64(p, 1));
        p = u64max(p, shfl_xor_u64(p, 2));
        if ((l & 3) == 0) {
            int row = rowblk * 128 + rloc + (bi >> 1) * 16 + (bi & 1) * 8;
            atomicMax(&g_best[row], p);
        }
        best[bi] = -2.0f; bidx[bi] = 0;
    }
}

// ---------------------------------------------------------------------------
// Kernel 2: persistent upper-tri GEMM-argmax with TWO independent warp teams.
__global__ void __launch_bounds__(NTHR, 1) koleo_gemm() {
    extern __shared__ __align__(16) char smem[];
    const uint32_t su = smem_u32(smem);
    const int tid = threadIdx.x;
    const int l   = tid & 31;
    const int wid = tid >> 5;
    const int team = wid >> 3;
    const int twid = wid & 7;
    const int wm  = twid >> 1;
    const int wn  = twid & 1;
    const int teamtid = tid & 255;
    const int rloc = wm * 32 + (l >> 2);
    const int b   = blockIdx.x;

    const uint32_t uTeamB = su + ATILE + (uint32_t)team * 2u * BTILE;

    const int cnt = 14 + (b < 8 ? 1 : 0);
    int s = b * 14 + (b < 8 ? b : 8);
    int i = 0;
    while (s >= 64 - i) { s -= 64 - i; i++; }
    int j = i + s;

    const uint32_t aoff = (uint32_t)((wm * 32 + (l & 15)) * RSB + (l >> 4) * 16);
    const uint32_t boff = (uint32_t)((wn * 32 + (l & 7) + ((l >> 4) << 3)) * RSB +
                                     ((l >> 3) & 1) * 16);

    // initial loads
    #pragma unroll
    for (int q = 0; q < 8; q++) {
        int flat = tid + q * NTHR;
        int r = flat >> 5;
        int c = flat & 31;
        CP16(su + r * RSB + c * 16,
             g_xh + (size_t)i * 128 * DIM + (size_t)r * DIM + c * 8);
    }
    if (j != i) {
        #pragma unroll
        for (int q = 0; q < 8; q++) {
            int flat = teamtid + q * 256;
            int r = flat >> 5;
            int c = flat & 31;
            CP16(uTeamB + r * RSB + c * 16,
                 g_xh + (size_t)(j * 128 + team * 64 + r) * DIM + c * 8);
        }
    }
    CPCOMMIT();
    CPWAIT0();
    __syncthreads();

    float best[4] = {-2.0f, -2.0f, -2.0f, -2.0f};
    int   bidx[4] = {0, 0, 0, 0};
    uint32_t c_[2][4][2];
    int curslot = 0;

    #pragma unroll 1
    for (int n = 0; n < cnt; n++) {
        const bool diag = (i == j);
        const int  colb = j * 128 + team * 64 + wn * 32 + (l & 3) * 2;
        const int  rbase = i * 128 + rloc;

        uint32_t uB, bo;
        if (diag) { uB = su; bo = boff + (uint32_t)(team * 64) * RSB; }
        else      { uB = uTeamB + (uint32_t)curslot * BTILE; bo = boff; }

        int ii2 = i, jj2 = j;
        bool rowchg = false;
        if (n + 1 < cnt) {
            if (j + 1 < 64) jj2 = j + 1;
            else { ii2 = i + 1; jj2 = i + 1; rowchg = true; }
        }
        const bool pf = (n + 1 < cnt) && !rowchg;
        const uint32_t pfdst = uTeamB + (uint32_t)(curslot ^ 1) * BTILE;
        const __half* pfsrc = g_xh + (size_t)(jj2 * 128 + team * 64) * DIM;

        mma_tile(c_, su, uB, aoff, bo, pf, pfdst, pfsrc, teamtid);
        if (pf) CPCOMMIT();
        fold_tile(c_, rbase, colb, diag, l, best, bidx);
        if (n + 1 == cnt || rowchg)
            flush_rows(i, rloc, l, best, bidx);

        if (n + 1 < cnt) {
            if (rowchg) {
                __syncthreads();
                #pragma unroll
                for (int q = 0; q < 8; q++) {
                    int flat = tid + q * NTHR;
                    int r = flat >> 5;
                    int c = flat & 31;
                    CP16(su + r * RSB + c * 16,
                         g_xh + (size_t)ii2 * 128 * DIM + (size_t)r * DIM + c * 8);
                }
                CPCOMMIT();
                CPWAIT0();
                __syncthreads();
                curslot = 0;
            } else {
                CPWAIT0();
                TEAMBAR(team);
                curslot ^= 1;
            }
        }
        i = ii2; j = jj2;
    }
}

// ---------------------------------------------------------------------------
// Kernel 3: per-row distance + log + fused reduction. One warp per row.
__global__ void koleo_dist(const float* __restrict__ x, float* __restrict__ out) {
    __shared__ float sh[8];
    int row  = blockIdx.x * 8 + (threadIdx.x >> 5);
    int lane = threadIdx.x & 31;
    int nb   = unpack_idx(g_best[row]);
    float ii = g_inv[row];
    float ij = g_inv[nb];
    const float4* xi = (const float4*)(x + (size_t)row * DIM);
    const float4* xj = (const float4*)(x + (size_t)nb  * DIM);
    float s = 0.0f;
    #pragma unroll
    for (int c = 0; c < 2; c++) {
        float4 a = xi[lane + c * 32];
        float4 b = xj[lane + c * 32];
        float d0 = a.x * ii - b.x * ij + kEPS, d1 = a.y * ii - b.y * ij + kEPS;
        float d2 = a.z * ii - b.z * ij + kEPS, d3 = a.w * ii - b.w * ij + kEPS;
        s = fmaf(d0, d0, s); s = fmaf(d1, d1, s);
        s = fmaf(d2, d2, s); s = fmaf(d3, d3, s);
    }
    #pragma unroll
    for (int o = 16; o > 0; o >>= 1) s += __shfl_xor_sync(0xffffffffu, s, o);
    if (lane == 0) sh[threadIdx.x >> 5] = logf(sqrtf(s) + kEPS);
    __syncthreads();
    if (threadIdx.x == 0) {
        float t = sh[0] + sh[1] + sh[2] + sh[3] + sh[4] + sh[5] + sh[6] + sh[7];
        atomicAdd(out, t * (-1.0f / (float)BROWS));
    }
}

// ---------------------------------------------------------------------------
extern "C" void kernel_launch(void* const* d_in, const int* in_sizes, int n_in,
                              void* d_out, int out_size) {
    const float* student = (const float*)d_in[0];
    float* out = (float*)d_out;
    (void)in_sizes; (void)n_in; (void)out_size;

    const int smem_bytes = ATILE + 4 * BTILE;   // 202752 B
    cudaFuncSetAttribute(koleo_gemm, cudaFuncAttributeMaxDynamicSharedMemorySize, smem_bytes);

    koleo_normcvt<<<BROWS / 16, 256>>>(student, out);
    koleo_gemm<<<NCTA, NTHR, smem_bytes>>>();
    koleo_dist<<<BROWS / 8, 256>>>(student, out);
}